// round 14
// baseline (speedup 1.0000x reference)
#include <cuda_runtime.h>

#define NCTA   128
#define NTHR   512
#define D      1024
#define BATCH  64
#define KT     64
#define NTILES 16
#define STR    68
#define SEQL   192
#define DECLEN 216
#define LABELN 48
#define PREDN  168

typedef unsigned long long ull;

// ---------------- persistent device state -----------------------------------
__device__ float    g_h0[2][BATCH * D];
__device__ float    g_h1[2][BATCH * D];
__device__ float    g_pred[BATCH * 8];
__device__ unsigned g_arrive;
__device__ unsigned g_release;

// ---------------- smem layout (floats) ---------------------------------------
// SW: 2*48*STR = 6528 | SH: 2*64*STR = 8704 | SX: 2*64*STR = 8704
// SXS: 768 | SRED: 128 | SWSM: 528   → total 25360 floats = 101440 B
#define SMEM_FLOATS 25360
extern __shared__ float smem[];
#define SW(buf)  (smem + (buf) * (48 * STR))
#define SH(buf)  (smem + 6528 + (buf) * (64 * STR))
#define SX(buf)  (smem + 15232 + (buf) * (64 * STR))
#define SXS      (smem + 23936)
#define SRED     (smem + 24704)
#define SWSM     (smem + 24832)

// ---------------- helpers ----------------------------------------------------
__device__ __forceinline__ void ffma2(ull& acc, ull a, ull b) {
    asm("fma.rn.f32x2 %0, %1, %2, %0;" : "+l"(acc) : "l"(a), "l"(b));
}
__device__ __forceinline__ float hadd2(ull v) {
    float lo, hi;
    asm("mov.b64 {%0,%1}, %2;" : "=f"(lo), "=f"(hi) : "l"(v));
    return lo + hi;
}
__device__ __forceinline__ float sigmoidf_(float x) {
    return 1.0f / (1.0f + __expf(-x));
}
__device__ __forceinline__ void cpasync16(float* sdst, const float* gsrc) {
    unsigned s = (unsigned)__cvta_generic_to_shared(sdst);
    asm volatile("cp.async.cg.shared.global [%0], [%1], 16;" :: "r"(s), "l"(gsrc));
}
#define CP_COMMIT()  asm volatile("cp.async.commit_group;" ::: "memory")
#define CP_WAIT0()   asm volatile("cp.async.wait_group 0;" ::: "memory")

// grid-wide barrier (all 128 CTAs co-resident; 1 CTA/SM, 128 <= 148 SMs)
__device__ __forceinline__ void grid_sync(unsigned barNo) {
    __syncthreads();
    if (threadIdx.x == 0) {
        __threadfence();
        unsigned a = atomicAdd(&g_arrive, 1u);
        if (a + 1u == barNo * (unsigned)NCTA) {
            __threadfence();
            atomicAdd(&g_release, 1u);
        } else {
            unsigned r;
            do {
                asm volatile("ld.acquire.gpu.u32 %0, [%1];" : "=r"(r) : "l"(&g_release));
            } while (r < barNo);
        }
    }
    __syncthreads();
}

// ---------------- tile staging (cp.async) ------------------------------------
template <bool HASX>
__device__ __forceinline__ void stage_tile(
    int buf, int kt, int tid, int col0,
    const float* __restrict__ Wih, const float* __restrict__ Whh,
    const float* __restrict__ hprev, const float* __restrict__ xfull)
{
    float* sh = SH(buf);
    float* sx = SX(buf);
    float* sw = SW(buf);
#pragma unroll
    for (int i = tid; i < BATCH * 16; i += NTHR) {
        int b = i >> 4, sg = i & 15;
        cpasync16(sh + b * STR + sg * 4, hprev + b * D + kt + sg * 4);
    }
    if (HASX) {
#pragma unroll
        for (int i = tid; i < BATCH * 16; i += NTHR) {
            int b = i >> 4, sg = i & 15;
            cpasync16(sx + b * STR + sg * 4, xfull + b * D + kt + sg * 4);
        }
    }
    const int NR = HASX ? 48 : 24;
    for (int i = tid; i < NR * 16; i += NTHR) {
        int r = i >> 4, sg = i & 15;
        const float* src = (HASX && r < 24) ? Wih : Whh;
        int rr = (HASX && r >= 24) ? (r - 24) : r;
        int g = rr >> 3, c = rr & 7;
        cpasync16(sw + r * STR + sg * 4,
                  src + (size_t)(g * D + col0 + c) * D + kt + sg * 4);
    }
}

// ---------------- one GRU layer step (this CTA's 8 columns) ------------------
// thread: bg = tid&7, cl = (tid>>3)&7, jh = tid>>6; owns (b = bg+8*jh, col0+cl)
template <bool HASX>
__device__ __forceinline__ void gru_layer(
    const float* __restrict__ Wih, const float* __restrict__ Whh,
    const float* __restrict__ bih, const float* __restrict__ bhh,
    const float* __restrict__ xfull,
    const float* __restrict__ hprev, float* __restrict__ hcur,
    const float* wsm_s,           // smem small-x weights (l0 only), else null
    int col0, int tid)
{
    const int bg = tid & 7;
    const int cl = (tid >> 3) & 7;
    const int jh = tid >> 6;
    const int b  = bg + 8 * jh;
    const int col = col0 + cl;
    const int hb  = HASX ? 24 : 0;
    const int hcoltile = col0 >> 6;
    const int hcolofs  = (col0 & 63) + cl;

    ull aR = 0, aZ = 0, aN = 0, aH = 0;
    float hp = 0.0f;

    stage_tile<HASX>(0, 0, tid, col0, Wih, Whh, hprev, xfull);
    CP_COMMIT();

    for (int tile = 0; tile < NTILES; tile++) {
        CP_WAIT0();
        __syncthreads();
        if (tile + 1 < NTILES) {
            stage_tile<HASX>((tile + 1) & 1, (tile + 1) * KT, tid, col0,
                             Wih, Whh, hprev, xfull);
            CP_COMMIT();
        }
        const float* sw = SW(tile & 1);
        const float* sh = SH(tile & 1);
        const float* sx = SX(tile & 1);
        if (tile == hcoltile) {
            hp = sh[b * STR + hcolofs];
        }
#pragma unroll 4
        for (int q = 0; q < KT / 4; q++) {
            const int o = 4 * q;
            ulonglong2 wHR = *(const ulonglong2*)(sw + (hb + cl) * STR + o);
            ulonglong2 wHZ = *(const ulonglong2*)(sw + (hb + 8 + cl) * STR + o);
            ulonglong2 wHN = *(const ulonglong2*)(sw + (hb + 16 + cl) * STR + o);
            ulonglong2 hv  = *(const ulonglong2*)(sh + b * STR + o);
            ffma2(aR, wHR.x, hv.x); ffma2(aR, wHR.y, hv.y);
            ffma2(aZ, wHZ.x, hv.x); ffma2(aZ, wHZ.y, hv.y);
            ffma2(aH, wHN.x, hv.x); ffma2(aH, wHN.y, hv.y);
            if (HASX) {
                ulonglong2 wIR = *(const ulonglong2*)(sw + cl * STR + o);
                ulonglong2 wIZ = *(const ulonglong2*)(sw + (8 + cl) * STR + o);
                ulonglong2 wIN = *(const ulonglong2*)(sw + (16 + cl) * STR + o);
                ulonglong2 xv  = *(const ulonglong2*)(sx + b * STR + o);
                ffma2(aR, wIR.x, xv.x); ffma2(aR, wIR.y, xv.y);
                ffma2(aZ, wIZ.x, xv.x); ffma2(aZ, wIZ.y, xv.y);
                ffma2(aN, wIN.x, xv.x); ffma2(aN, wIN.y, xv.y);
            }
        }
    }

    // ---- epilogue ----
    float br  = __ldg(bih + col)         + __ldg(bhh + col);
    float bz  = __ldg(bih + D + col)     + __ldg(bhh + D + col);
    float bni = __ldg(bih + 2 * D + col);
    float bnh = __ldg(bhh + 2 * D + col);

    float r   = hadd2(aR) + br;
    float z   = hadd2(aZ) + bz;
    float inn = hadd2(aN) + bni;
    float hn  = hadd2(aH) + bnh;
    if (!HASX) {
        const float* xs = &SXS[b * 12];
#pragma unroll
        for (int k = 0; k < 11; k++) {
            float xv = xs[k];
            r   += wsm_s[cl * 11 + k] * xv;
            z   += wsm_s[88 + cl * 11 + k] * xv;
            inn += wsm_s[176 + cl * 11 + k] * xv;
        }
    }
    r = sigmoidf_(r);
    z = sigmoidf_(z);
    float n = tanhf(inn + r * hn);
    hcur[b * D + col] = (1.0f - z) * n + z * hp;
}

// ---------------- init ------------------------------------------------------
__global__ void gru_init_kernel() {
    int i = blockIdx.x * blockDim.x + threadIdx.x;
    int n = 2 * BATCH * D;
    float* a = &g_h0[0][0];
    float* b = &g_h1[0][0];
    if (i < n) { a[i] = 0.0f; b[i] = 0.0f; }
    if (i < BATCH * 8) g_pred[i] = 0.0f;
    if (i == 0) { g_arrive = 0u; g_release = 0u; }
}

// ---------------- main persistent kernel ------------------------------------
__global__ void __launch_bounds__(NTHR, 1) gru_persistent_kernel(
    const float* __restrict__ xe,  const float* __restrict__ xme,
    const float* __restrict__ xd,  const float* __restrict__ xmd,
    const float* __restrict__ eWih0, const float* __restrict__ eWhh0,
    const float* __restrict__ ebih0, const float* __restrict__ ebhh0,
    const float* __restrict__ eWih1, const float* __restrict__ eWhh1,
    const float* __restrict__ ebih1, const float* __restrict__ ebhh1,
    const float* __restrict__ dWih0, const float* __restrict__ dWhh0,
    const float* __restrict__ dbih0, const float* __restrict__ dbhh0,
    const float* __restrict__ dWih1, const float* __restrict__ dWhh1,
    const float* __restrict__ dbih1, const float* __restrict__ dbhh1,
    const float* __restrict__ outW,  const float* __restrict__ outb,
    float* __restrict__ out)
{
    const int tid  = threadIdx.x;
    const int col0 = blockIdx.x * 8;
    unsigned barNo = 0;
    int p = 0;

    // preload small-x weights (l0 enc + l0 dec) into smem once
    for (int i = tid; i < 264; i += NTHR) {
        int g = i / 88, r2 = i - g * 88;
        int c = r2 / 11, k = r2 - c * 11;
        SWSM[i]       = __ldg(eWih0 + (size_t)(g * D + col0 + c) * 11 + k);
        SWSM[264 + i] = __ldg(dWih0 + (size_t)(g * D + col0 + c) * 11 + k);
    }
    __syncthreads();

    // ================= encoder =================
    for (int t = 0; t < SEQL; t++) {
        for (int i = tid; i < BATCH * 11; i += NTHR) {
            int b = i / 11, k = i - b * 11;
            float v = (k < 7) ? __ldg(xe + (size_t)(b * SEQL + t) * 7 + k)
                              : __ldg(xme + (size_t)(b * SEQL + t) * 4 + (k - 7));
            SXS[b * 12 + k] = v;
        }
        gru_layer<false>(eWih0, eWhh0, ebih0, ebhh0, nullptr,
                         g_h0[p], g_h0[1 - p], SWSM, col0, tid);
        barNo++; grid_sync(barNo);
        gru_layer<true>(eWih1, eWhh1, ebih1, ebhh1,
                        g_h0[1 - p], g_h1[p], g_h1[1 - p], nullptr, col0, tid);
        barNo++; grid_sync(barNo);
        p ^= 1;
    }

    // ================= decoder =================
    for (int t = 0; t < DECLEN; t++) {
        for (int i = tid; i < BATCH * 11; i += NTHR) {
            int b = i / 11, k = i - b * 11;
            float v;
            if (k >= 7)          v = __ldg(xmd + (size_t)(b * DECLEN + t) * 4 + (k - 7));
            else if (t < LABELN) v = __ldg(xd + (size_t)(b * DECLEN + t) * 7 + k);
            else                 v = __ldcg(g_pred + b * 8 + k);
            SXS[b * 12 + k] = v;
        }
        gru_layer<false>(dWih0, dWhh0, dbih0, dbhh0, nullptr,
                         g_h0[p], g_h0[1 - p], SWSM + 264, col0, tid);
        barNo++; grid_sync(barNo);
        gru_layer<true>(dWih1, dWhh1, dbih1, dbhh1,
                        g_h0[1 - p], g_h1[p], g_h1[1 - p], nullptr, col0, tid);
        barNo++; grid_sync(barNo);

        // output projection: CTA b (< 64) computes pred[b][0..6]
        if (blockIdx.x < BATCH) {
            int b = blockIdx.x;
            const float* h1c = g_h1[1 - p];
            float acc[7] = {0, 0, 0, 0, 0, 0, 0};
#pragma unroll
            for (int kb = 0; kb < 2; kb++) {
                int k = kb * NTHR + tid;
                float hv = __ldcg(h1c + b * D + k);
#pragma unroll
                for (int j = 0; j < 7; j++)
                    acc[j] += __ldg(outW + j * D + k) * hv;
            }
#pragma unroll
            for (int j = 0; j < 7; j++)
                for (int off = 16; off; off >>= 1)
                    acc[j] += __shfl_down_sync(0xffffffffu, acc[j], off);
            int lane = tid & 31, w = tid >> 5;
            if (lane == 0) {
#pragma unroll
                for (int j = 0; j < 7; j++) SRED[w * 7 + j] = acc[j];
            }
            __syncthreads();
            if (tid < 7) {
                float s = __ldg(outb + tid);
#pragma unroll
                for (int w2 = 0; w2 < 16; w2++) s += SRED[w2 * 7 + tid];
                g_pred[b * 8 + tid] = s;
                if (t >= LABELN)
                    out[(size_t)b * (PREDN * 7) + (t - LABELN) * 7 + tid] = s;
            }
        }
        barNo++; grid_sync(barNo);
        p ^= 1;
    }
}

// ---------------- launch -----------------------------------------------------
extern "C" void kernel_launch(void* const* d_in, const int* in_sizes, int n_in,
                              void* d_out, int out_size) {
    (void)in_sizes; (void)n_in; (void)out_size;
    const float* xe    = (const float*)d_in[0];
    const float* xme   = (const float*)d_in[1];
    const float* xd    = (const float*)d_in[2];
    const float* xmd   = (const float*)d_in[3];
    const float* eWih0 = (const float*)d_in[4];
    const float* eWhh0 = (const float*)d_in[5];
    const float* ebih0 = (const float*)d_in[6];
    const float* ebhh0 = (const float*)d_in[7];
    const float* eWih1 = (const float*)d_in[8];
    const float* eWhh1 = (const float*)d_in[9];
    const float* ebih1 = (const float*)d_in[10];
    const float* ebhh1 = (const float*)d_in[11];
    const float* dWih0 = (const float*)d_in[12];
    const float* dWhh0 = (const float*)d_in[13];
    const float* dbih0 = (const float*)d_in[14];
    const float* dbhh0 = (const float*)d_in[15];
    const float* dWih1 = (const float*)d_in[16];
    const float* dWhh1 = (const float*)d_in[17];
    const float* dbih1 = (const float*)d_in[18];
    const float* dbhh1 = (const float*)d_in[19];
    const float* outW  = (const float*)d_in[20];
    const float* outb  = (const float*)d_in[21];

    static int attr_set = 0;
    if (!attr_set) {
        cudaFuncSetAttribute(gru_persistent_kernel,
                             cudaFuncAttributeMaxDynamicSharedMemorySize,
                             SMEM_FLOATS * (int)sizeof(float));
        attr_set = 1;
    }

    gru_init_kernel<<<(2 * BATCH * D + 255) / 256, 256>>>();
    gru_persistent_kernel<<<NCTA, NTHR, SMEM_FLOATS * sizeof(float)>>>(
        xe, xme, xd, xmd,
        eWih0, eWhh0, ebih0, ebhh0, eWih1, eWhh1, ebih1, ebhh1,
        dWih0, dWhh0, dbih0, dbhh0, dWih1, dWhh1, dbih1, dbhh1,
        outW, outb, (float*)d_out);
}

// round 15
// speedup vs baseline: 1.2682x; 1.2682x over previous
#include <cuda_runtime.h>

#define NCTA   128
#define NTHR   512
#define GSZ    256          // threads per K-group
#define D      1024
#define KHALF  512
#define BATCH  64
#define KT     64
#define NT_G   8            // tiles per K-group
#define STR    68
#define SEQL   192
#define DECLEN 216
#define LABELN 48
#define PREDN  168

typedef unsigned long long ull;

// ---------------- persistent device state -----------------------------------
__device__ float    g_h0[2][BATCH * D];
__device__ float    g_h1[2][BATCH * D];
__device__ float    g_pred[BATCH * 8];
__device__ unsigned g_arrive;
__device__ unsigned g_release;

// ---------------- smem layout (floats) ---------------------------------------
// per K-group block (23936 floats):
//   SW: 2*48*STR = 6528 | SH: 2*64*STR = 8704 | SX: 2*64*STR = 8704
// then: SXS 768 | SRED 128 | SWSM 528 | SPART 2048
// total = 2*23936 + 3472 = 51344 floats = 205376 B
#define GBLK 23936
#define SMEM_FLOATS 51344
extern __shared__ float smem[];
#define SW(g,buf)  (smem + (g) * GBLK + (buf) * (48 * STR))
#define SH(g,buf)  (smem + (g) * GBLK + 6528 + (buf) * (64 * STR))
#define SX(g,buf)  (smem + (g) * GBLK + 15232 + (buf) * (64 * STR))
#define SXS        (smem + 2 * GBLK)
#define SRED       (smem + 2 * GBLK + 768)
#define SWSM       (smem + 2 * GBLK + 896)
#define SPART      (smem + 2 * GBLK + 1424)

// ---------------- helpers ----------------------------------------------------
__device__ __forceinline__ void ffma2(ull& acc, ull a, ull b) {
    asm("fma.rn.f32x2 %0, %1, %2, %0;" : "+l"(acc) : "l"(a), "l"(b));
}
__device__ __forceinline__ float hadd2(ull v) {
    float lo, hi;
    asm("mov.b64 {%0,%1}, %2;" : "=f"(lo), "=f"(hi) : "l"(v));
    return lo + hi;
}
__device__ __forceinline__ float sigmoidf_(float x) {
    return 1.0f / (1.0f + __expf(-x));
}
__device__ __forceinline__ void cpasync16(float* sdst, const float* gsrc) {
    unsigned s = (unsigned)__cvta_generic_to_shared(sdst);
    asm volatile("cp.async.cg.shared.global [%0], [%1], 16;" :: "r"(s), "l"(gsrc));
}
#define CP_COMMIT()  asm volatile("cp.async.commit_group;" ::: "memory")
#define CP_WAIT0()   asm volatile("cp.async.wait_group 0;" ::: "memory")

// grid-wide barrier (128 CTAs, 1/SM, all co-resident)
__device__ __forceinline__ void grid_sync(unsigned barNo) {
    __syncthreads();
    if (threadIdx.x == 0) {
        __threadfence();
        unsigned a = atomicAdd(&g_arrive, 1u);
        if (a + 1u == barNo * (unsigned)NCTA) {
            __threadfence();
            atomicAdd(&g_release, 1u);
        } else {
            unsigned r;
            do {
                asm volatile("ld.acquire.gpu.u32 %0, [%1];" : "=r"(r) : "l"(&g_release));
            } while (r < barNo);
        }
    }
    __syncthreads();
}

// ---------------- tile staging (cp.async), one K-group -----------------------
template <bool HASX>
__device__ __forceinline__ void stage_tile(
    int g, int buf, int ktg, int t8, int col0,
    const float* __restrict__ Wih, const float* __restrict__ Whh,
    const float* __restrict__ hprev, const float* __restrict__ xfull)
{
    float* sh = SH(g, buf);
    float* sx = SX(g, buf);
    float* sw = SW(g, buf);
#pragma unroll
    for (int i = t8; i < BATCH * 16; i += GSZ) {
        int b = i >> 4, sg = i & 15;
        cpasync16(sh + b * STR + sg * 4, hprev + b * D + ktg + sg * 4);
    }
    if (HASX) {
#pragma unroll
        for (int i = t8; i < BATCH * 16; i += GSZ) {
            int b = i >> 4, sg = i & 15;
            cpasync16(sx + b * STR + sg * 4, xfull + b * D + ktg + sg * 4);
        }
    }
    const int NR = HASX ? 48 : 24;
    for (int i = t8; i < NR * 16; i += GSZ) {
        int r = i >> 4, sg = i & 15;
        const float* src = (HASX && r < 24) ? Wih : Whh;
        int rr = (HASX && r >= 24) ? (r - 24) : r;
        int gg = rr >> 3, c = rr & 7;
        cpasync16(sw + r * STR + sg * 4,
                  src + (size_t)(gg * D + col0 + c) * D + ktg + sg * 4);
    }
}

// ---------------- one GRU layer step (this CTA's 8 columns) ------------------
// tid: g = tid>>8 (K-group); t8 = tid&255: bg=t8&7, cl=(t8>>3)&7, jh=t8>>6
// thread pair set: (col0+cl, b0=bg+16*jh) and (col0+cl, b1=b0+8); K-range by g.
template <bool HASX>
__device__ __forceinline__ void gru_layer(
    const float* __restrict__ Wih, const float* __restrict__ Whh,
    const float* __restrict__ bih, const float* __restrict__ bhh,
    const float* __restrict__ xfull,
    const float* __restrict__ hprev, float* __restrict__ hcur,
    const float* wsm_s, int col0, int tid)
{
    const int g  = tid >> 8;
    const int t8 = tid & 255;
    const int bg = t8 & 7;
    const int cl = (t8 >> 3) & 7;
    const int jh = t8 >> 6;
    const int b0 = bg + 16 * jh;
    const int b1 = b0 + 8;
    const int col = col0 + cl;
    const int hb  = HASX ? 24 : 0;

    ull aR0 = 0, aZ0 = 0, aN0 = 0, aH0 = 0;
    ull aR1 = 0, aZ1 = 0, aN1 = 0, aH1 = 0;

    // prefetch h_prev for the state update (needed only in the epilogue;
    // issue now so the L2 latency is fully hidden behind the tile loop)
    float hp0 = 0.0f, hp1 = 0.0f;
    if (g == 0) {
        hp0 = __ldcg(hprev + b0 * D + col);
        hp1 = __ldcg(hprev + b1 * D + col);
    }

    stage_tile<HASX>(g, 0, g * KHALF, t8, col0, Wih, Whh, hprev, xfull);
    CP_COMMIT();

    for (int tile = 0; tile < NT_G; tile++) {
        CP_WAIT0();
        __syncthreads();
        if (tile + 1 < NT_G) {
            stage_tile<HASX>(g, (tile + 1) & 1, g * KHALF + (tile + 1) * KT,
                             t8, col0, Wih, Whh, hprev, xfull);
            CP_COMMIT();
        }
        const float* sw = SW(g, tile & 1);
        const float* sh = SH(g, tile & 1);
        const float* sx = SX(g, tile & 1);
#pragma unroll 4
        for (int q = 0; q < KT / 4; q++) {
            const int o = 4 * q;
            ulonglong2 wHR = *(const ulonglong2*)(sw + (hb + cl) * STR + o);
            ulonglong2 wHZ = *(const ulonglong2*)(sw + (hb + 8 + cl) * STR + o);
            ulonglong2 wHN = *(const ulonglong2*)(sw + (hb + 16 + cl) * STR + o);
            ulonglong2 h0v = *(const ulonglong2*)(sh + b0 * STR + o);
            ulonglong2 h1v = *(const ulonglong2*)(sh + b1 * STR + o);
            ffma2(aR0, wHR.x, h0v.x); ffma2(aR0, wHR.y, h0v.y);
            ffma2(aZ0, wHZ.x, h0v.x); ffma2(aZ0, wHZ.y, h0v.y);
            ffma2(aH0, wHN.x, h0v.x); ffma2(aH0, wHN.y, h0v.y);
            ffma2(aR1, wHR.x, h1v.x); ffma2(aR1, wHR.y, h1v.y);
            ffma2(aZ1, wHZ.x, h1v.x); ffma2(aZ1, wHZ.y, h1v.y);
            ffma2(aH1, wHN.x, h1v.x); ffma2(aH1, wHN.y, h1v.y);
            if (HASX) {
                ulonglong2 wIR = *(const ulonglong2*)(sw + cl * STR + o);
                ulonglong2 wIZ = *(const ulonglong2*)(sw + (8 + cl) * STR + o);
                ulonglong2 wIN = *(const ulonglong2*)(sw + (16 + cl) * STR + o);
                ulonglong2 x0v = *(const ulonglong2*)(sx + b0 * STR + o);
                ulonglong2 x1v = *(const ulonglong2*)(sx + b1 * STR + o);
                ffma2(aR0, wIR.x, x0v.x); ffma2(aR0, wIR.y, x0v.y);
                ffma2(aZ0, wIZ.x, x0v.x); ffma2(aZ0, wIZ.y, x0v.y);
                ffma2(aN0, wIN.x, x0v.x); ffma2(aN0, wIN.y, x0v.y);
                ffma2(aR1, wIR.x, x1v.x); ffma2(aR1, wIR.y, x1v.y);
                ffma2(aZ1, wIZ.x, x1v.x); ffma2(aZ1, wIZ.y, x1v.y);
                ffma2(aN1, wIN.x, x1v.x); ffma2(aN1, wIN.y, x1v.y);
            }
        }
    }

    // ---- cross-K-group reduction: group 1 publishes partials ----
    if (g == 1) {
        int pid0 = cl * 64 + b0, pid1 = cl * 64 + b1;
        *(float4*)(SPART + pid0 * 4) =
            make_float4(hadd2(aR0), hadd2(aZ0), hadd2(aN0), hadd2(aH0));
        *(float4*)(SPART + pid1 * 4) =
            make_float4(hadd2(aR1), hadd2(aZ1), hadd2(aN1), hadd2(aH1));
    }
    __syncthreads();

    // ---- epilogue (group 0 only) ----
    if (g == 0) {
        float br  = __ldg(bih + col)         + __ldg(bhh + col);
        float bz  = __ldg(bih + D + col)     + __ldg(bhh + D + col);
        float bni = __ldg(bih + 2 * D + col);
        float bnh = __ldg(bhh + 2 * D + col);

#pragma unroll
        for (int i = 0; i < 2; i++) {
            int b = i ? b1 : b0;
            float4 pp = *(const float4*)(SPART + (cl * 64 + b) * 4);
            float r   = hadd2(i ? aR1 : aR0) + pp.x + br;
            float z   = hadd2(i ? aZ1 : aZ0) + pp.y + bz;
            float inn = hadd2(i ? aN1 : aN0) + pp.z + bni;
            float hn  = hadd2(i ? aH1 : aH0) + pp.w + bnh;
            if (!HASX) {
                const float* xs = &SXS[b * 12];
#pragma unroll
                for (int k = 0; k < 11; k++) {
                    float xv = xs[k];
                    r   += wsm_s[cl * 11 + k] * xv;
                    z   += wsm_s[88 + cl * 11 + k] * xv;
                    inn += wsm_s[176 + cl * 11 + k] * xv;
                }
            }
            r = sigmoidf_(r);
            z = sigmoidf_(z);
            float n  = tanhf(inn + r * hn);
            float hp = i ? hp1 : hp0;
            hcur[b * D + col] = (1.0f - z) * n + z * hp;
        }
    }
}

// ---------------- init ------------------------------------------------------
__global__ void gru_init_kernel() {
    int i = blockIdx.x * blockDim.x + threadIdx.x;
    int n = 2 * BATCH * D;
    float* a = &g_h0[0][0];
    float* b = &g_h1[0][0];
    if (i < n) { a[i] = 0.0f; b[i] = 0.0f; }
    if (i < BATCH * 8) g_pred[i] = 0.0f;
    if (i == 0) { g_arrive = 0u; g_release = 0u; }
}

// ---------------- main persistent kernel ------------------------------------
__global__ void __launch_bounds__(NTHR, 1) gru_persistent_kernel(
    const float* __restrict__ xe,  const float* __restrict__ xme,
    const float* __restrict__ xd,  const float* __restrict__ xmd,
    const float* __restrict__ eWih0, const float* __restrict__ eWhh0,
    const float* __restrict__ ebih0, const float* __restrict__ ebhh0,
    const float* __restrict__ eWih1, const float* __restrict__ eWhh1,
    const float* __restrict__ ebih1, const float* __restrict__ ebhh1,
    const float* __restrict__ dWih0, const float* __restrict__ dWhh0,
    const float* __restrict__ dbih0, const float* __restrict__ dbhh0,
    const float* __restrict__ dWih1, const float* __restrict__ dWhh1,
    const float* __restrict__ dbih1, const float* __restrict__ dbhh1,
    const float* __restrict__ outW,  const float* __restrict__ outb,
    float* __restrict__ out)
{
    const int tid  = threadIdx.x;
    const int col0 = blockIdx.x * 8;
    unsigned barNo = 0;
    int p = 0;

    // preload small-x weights (l0 enc + l0 dec) into smem once
    for (int i = tid; i < 264; i += NTHR) {
        int g = i / 88, r2 = i - g * 88;
        int c = r2 / 11, k = r2 - c * 11;
        SWSM[i]       = __ldg(eWih0 + (size_t)(g * D + col0 + c) * 11 + k);
        SWSM[264 + i] = __ldg(dWih0 + (size_t)(g * D + col0 + c) * 11 + k);
    }
    __syncthreads();

    // ================= encoder =================
    for (int t = 0; t < SEQL; t++) {
        for (int i = tid; i < BATCH * 11; i += NTHR) {
            int b = i / 11, k = i - b * 11;
            float v = (k < 7) ? __ldg(xe + (size_t)(b * SEQL + t) * 7 + k)
                              : __ldg(xme + (size_t)(b * SEQL + t) * 4 + (k - 7));
            SXS[b * 12 + k] = v;
        }
        __syncthreads();
        gru_layer<false>(eWih0, eWhh0, ebih0, ebhh0, nullptr,
                         g_h0[p], g_h0[1 - p], SWSM, col0, tid);
        barNo++; grid_sync(barNo);
        gru_layer<true>(eWih1, eWhh1, ebih1, ebhh1,
                        g_h0[1 - p], g_h1[p], g_h1[1 - p], nullptr, col0, tid);
        barNo++; grid_sync(barNo);
        p ^= 1;
    }

    // ================= decoder =================
    for (int t = 0; t < DECLEN; t++) {
        for (int i = tid; i < BATCH * 11; i += NTHR) {
            int b = i / 11, k = i - b * 11;
            float v;
            if (k >= 7)          v = __ldg(xmd + (size_t)(b * DECLEN + t) * 4 + (k - 7));
            else if (t < LABELN) v = __ldg(xd + (size_t)(b * DECLEN + t) * 7 + k);
            else                 v = __ldcg(g_pred + b * 8 + k);
            SXS[b * 12 + k] = v;
        }
        __syncthreads();
        gru_layer<false>(dWih0, dWhh0, dbih0, dbhh0, nullptr,
                         g_h0[p], g_h0[1 - p], SWSM + 264, col0, tid);
        barNo++; grid_sync(barNo);
        gru_layer<true>(dWih1, dWhh1, dbih1, dbhh1,
                        g_h0[1 - p], g_h1[p], g_h1[1 - p], nullptr, col0, tid);
        barNo++; grid_sync(barNo);

        // output projection: CTA b (< 64) computes pred[b][0..6]
        if (blockIdx.x < BATCH) {
            int b = blockIdx.x;
            const float* h1c = g_h1[1 - p];
            float acc[7] = {0, 0, 0, 0, 0, 0, 0};
#pragma unroll
            for (int kb = 0; kb < 2; kb++) {
                int k = kb * NTHR + tid;
                float hv = __ldcg(h1c + b * D + k);
#pragma unroll
                for (int j = 0; j < 7; j++)
                    acc[j] += __ldg(outW + j * D + k) * hv;
            }
#pragma unroll
            for (int j = 0; j < 7; j++)
                for (int off = 16; off; off >>= 1)
                    acc[j] += __shfl_down_sync(0xffffffffu, acc[j], off);
            int lane = tid & 31, w = tid >> 5;
            if (lane == 0) {
#pragma unroll
                for (int j = 0; j < 7; j++) SRED[w * 7 + j] = acc[j];
            }
            __syncthreads();
            if (tid < 7) {
                float s = __ldg(outb + tid);
#pragma unroll
                for (int w2 = 0; w2 < 16; w2++) s += SRED[w2 * 7 + tid];
                g_pred[b * 8 + tid] = s;
                if (t >= LABELN)
                    out[(size_t)b * (PREDN * 7) + (t - LABELN) * 7 + tid] = s;
            }
        }
        barNo++; grid_sync(barNo);
        p ^= 1;
    }
}

// ---------------- launch -----------------------------------------------------
extern "C" void kernel_launch(void* const* d_in, const int* in_sizes, int n_in,
                              void* d_out, int out_size) {
    (void)in_sizes; (void)n_in; (void)out_size;
    const float* xe    = (const float*)d_in[0];
    const float* xme   = (const float*)d_in[1];
    const float* xd    = (const float*)d_in[2];
    const float* xmd   = (const float*)d_in[3];
    const float* eWih0 = (const float*)d_in[4];
    const float* eWhh0 = (const float*)d_in[5];
    const float* ebih0 = (const float*)d_in[6];
    const float* ebhh0 = (const float*)d_in[7];
    const float* eWih1 = (const float*)d_in[8];
    const float* eWhh1 = (const float*)d_in[9];
    const float* ebih1 = (const float*)d_in[10];
    const float* ebhh1 = (const float*)d_in[11];
    const float* dWih0 = (const float*)d_in[12];
    const float* dWhh0 = (const float*)d_in[13];
    const float* dbih0 = (const float*)d_in[14];
    const float* dbhh0 = (const float*)d_in[15];
    const float* dWih1 = (const float*)d_in[16];
    const float* dWhh1 = (const float*)d_in[17];
    const float* dbih1 = (const float*)d_in[18];
    const float* dbhh1 = (const float*)d_in[19];
    const float* outW  = (const float*)d_in[20];
    const float* outb  = (const float*)d_in[21];

    static int attr_set = 0;
    if (!attr_set) {
        cudaFuncSetAttribute(gru_persistent_kernel,
                             cudaFuncAttributeMaxDynamicSharedMemorySize,
                             SMEM_FLOATS * (int)sizeof(float));
        attr_set = 1;
    }

    gru_init_kernel<<<(2 * BATCH * D + 255) / 256, 256>>>();
    gru_persistent_kernel<<<NCTA, NTHR, SMEM_FLOATS * sizeof(float)>>>(
        xe, xme, xd, xmd,
        eWih0, eWhh0, ebih0, ebhh0, eWih1, eWhh1, ebih1, ebhh1,
        dWih0, dWhh0, dbih0, dbhh0, dWih1, dWhh1, dbih1, dbhh1,
        outW, outb, (float*)d_out);
}